// round 2
// baseline (speedup 1.0000x reference)
#include <cuda_runtime.h>
#include <cuda_bf16.h>
#include <cstdint>

// Top-1 MoE router (s=8192 tokens, e=64 experts, capacity=160).
// Outputs (concatenated float32, order per reference return):
//   combine_weights [s, e, c]   (83886080 elems)
//   sec_mask        [s, e, c]   (0/1 as float, optional per out_size)
//   exp_counts      [e]         (as float, optional per out_size)
//
// Strategy: output is >99.99% zeros -> cudaMemsetAsync the whole buffer,
// then scatter the <=8192 nonzero entries.

#define S 8192
#define E 64
#define CAP 160
#define CW_N 83886080LL  // S*E*CAP

// ---- device scratch (no allocations allowed) ----
__device__ int   g_cnt[E];
__device__ int   g_list[E][S];          // token ids per expert (order nondeterministic)
__device__ float g_prob[S];             // softmax prob at argmax expert
__device__ unsigned char g_kept[E][S];  // fallback kept flags (large-n path)

// ---------------------------------------------------------------
__global__ void zero_counts_kernel() {
    if (threadIdx.x < E) g_cnt[threadIdx.x] = 0;
}

// One warp per token: argmax over 64 experts (tie -> lowest index),
// softmax prob at argmax = 1 / sum(exp(x - max)).
__global__ void route_kernel(const float* __restrict__ x) {
    int token = blockIdx.x * (blockDim.x / 32) + (threadIdx.x >> 5);
    if (token >= S) return;
    int lane = threadIdx.x & 31;
    const float* row = x + (long long)token * E;
    float v0 = row[lane];
    float v1 = row[lane + 32];

    float bv; int bi;
    if (v1 > v0) { bv = v1; bi = lane + 32; } else { bv = v0; bi = lane; }
    #pragma unroll
    for (int o = 16; o; o >>= 1) {
        float ov = __shfl_xor_sync(0xffffffffu, bv, o);
        int   oi = __shfl_xor_sync(0xffffffffu, bi, o);
        if (ov > bv || (ov == bv && oi < bi)) { bv = ov; bi = oi; }
    }
    float s = __expf(v0 - bv) + __expf(v1 - bv);
    #pragma unroll
    for (int o = 16; o; o >>= 1) s += __shfl_xor_sync(0xffffffffu, s, o);

    if (lane == 0) {
        g_prob[token] = 1.0f / s;
        int slot = atomicAdd(&g_cnt[bi], 1);
        g_list[bi][slot] = token;
    }
}

// One block per expert: capacity selection (top-CAP by rand, tie -> lower
// token index), loc = rank by token index among kept, then scatter.
#define MAXN 2048
__global__ void select_scatter_kernel(const float* __restrict__ rnd,
                                      float* __restrict__ out,
                                      long long mask_off, long long counts_off) {
    int e = blockIdx.x;
    int n = g_cnt[e];

    __shared__ float sr[MAXN];
    __shared__ int   st[MAXN];
    __shared__ unsigned char sk[MAXN];

    if (n <= MAXN) {
        for (int i = threadIdx.x; i < n; i += blockDim.x) {
            int t = g_list[e][i];
            st[i] = t;
            sr[i] = rnd[(long long)t * E + e];
        }
        __syncthreads();
        // rank among this expert's assigned tokens (descending rand,
        // tie -> lower token index, matching jax.lax.top_k)
        for (int i = threadIdx.x; i < n; i += blockDim.x) {
            float rj = sr[i]; int tj = st[i];
            int rank = 0;
            for (int k = 0; k < n; k++) {
                float rk = sr[k];
                rank += (rk > rj) || (rk == rj && st[k] < tj);
            }
            sk[i] = (rank < CAP) ? 1 : 0;
        }
        __syncthreads();
        for (int i = threadIdx.x; i < n; i += blockDim.x) {
            if (!sk[i]) continue;
            int tj = st[i];
            int loc = 0;
            for (int k = 0; k < n; k++) loc += (sk[k] && (st[k] < tj)) ? 1 : 0;
            long long base = (long long)tj * (E * CAP) + (long long)e * CAP + loc;
            out[base] = g_prob[tj];
            if (mask_off >= 0) out[mask_off + base] = 1.0f;
        }
    } else {
        // robust fallback for pathological counts (> MAXN); O(n^2) global reads
        for (int i = threadIdx.x; i < n; i += blockDim.x) {
            int tj = g_list[e][i];
            float rj = rnd[(long long)tj * E + e];
            int rank = 0;
            for (int k = 0; k < n; k++) {
                int tk = g_list[e][k];
                float rk = rnd[(long long)tk * E + e];
                rank += (rk > rj) || (rk == rj && tk < tj);
            }
            g_kept[e][i] = (rank < CAP) ? 1 : 0;
        }
        __syncthreads();
        for (int i = threadIdx.x; i < n; i += blockDim.x) {
            if (!g_kept[e][i]) continue;
            int tj = g_list[e][i];
            int loc = 0;
            for (int k = 0; k < n; k++)
                loc += (g_kept[e][k] && (g_list[e][k] < tj)) ? 1 : 0;
            long long base = (long long)tj * (E * CAP) + (long long)e * CAP + loc;
            out[base] = g_prob[tj];
            if (mask_off >= 0) out[mask_off + base] = 1.0f;
        }
    }

    if (threadIdx.x == 0 && counts_off >= 0) out[counts_off + e] = (float)n;
}

// ---------------------------------------------------------------
extern "C" void kernel_launch(void* const* d_in, const int* in_sizes, int n_in,
                              void* d_out, int out_size) {
    const float* x   = (const float*)d_in[0];
    const float* rnd = (const float*)d_in[1];
    float* out = (float*)d_out;

    long long osz = (long long)out_size;
    long long mask_off = -1, counts_off = -1;
    if (osz == CW_N) {
        // combine_weights only
    } else if (osz == CW_N + E) {
        counts_off = CW_N;
    } else if (osz == 2 * CW_N) {
        mask_off = CW_N;
    } else if (osz == 2 * CW_N + E) {
        mask_off = CW_N;
        counts_off = 2 * CW_N;
    } else {
        // best-effort generic layout guess
        if (osz >= 2 * CW_N) mask_off = CW_N;
        if (((osz - E) % CW_N) == 0) counts_off = osz - E;
    }

    // zero the entire (mostly-zero) output, then scatter nonzeros
    cudaMemsetAsync(d_out, 0, (size_t)osz * sizeof(float), 0);
    zero_counts_kernel<<<1, 64>>>();
    route_kernel<<<(S * 32 + 255) / 256, 256>>>(x);
    select_scatter_kernel<<<E, 256>>>(rnd, out, mask_off, counts_off);
}